// round 6
// baseline (speedup 1.0000x reference)
#include <cuda_runtime.h>
#include <cstdint>
#include <cstddef>

#define BATCH 8
#define SEQ   1024
#define HID   768
#define ENT   9
#define DIM   64

// ---------------- device scratch (static: no allocation allowed) ----------------
__device__ float g_q[BATCH * ENT * SEQ * DIM];   // [B,E,S,D]  (1/8 scale folded in)
__device__ float g_k[BATCH * ENT * SEQ * DIM];   // [B,E,S,D]
__device__ float g_cos[SEQ * 32];
__device__ float g_sin[SEQ * 32];

typedef unsigned long long ull;

// ---------------- packed f32x2 helpers (Blackwell FFMA2 path) ----------------
__device__ __forceinline__ ull ffma2(ull a, ull b, ull c) {
    ull d;
    asm("fma.rn.f32x2 %0, %1, %2, %3;" : "=l"(d) : "l"(a), "l"(b), "l"(c));
    return d;
}
__device__ __forceinline__ ull dup2(float x) {
    ull r;
    asm("mov.b64 %0, {%1, %1};" : "=l"(r) : "f"(x));
    return r;
}
__device__ __forceinline__ void unpack2(ull v, float& lo, float& hi) {
    asm("mov.b64 {%0, %1}, %2;" : "=f"(lo), "=f"(hi) : "l"(v));
}

// ---------------- RoPE sin/cos table (fp64 for robustness vs fast-math) ----------------
__global__ void rope_table_kernel() {
    int idx = blockIdx.x * blockDim.x + threadIdx.x;
    if (idx >= SEQ * 32) return;
    int pos = idx >> 5;
    int j   = idx & 31;
    double inv = pow(10000.0, -(double)j / 32.0);   // 10000^(-2j/64)
    double ang = (double)pos * inv;
    g_cos[idx] = (float)cos(ang);
    g_sin[idx] = (float)sin(ang);
}

// ---------------- Kernel A: X @ W^T + b, RoPE, scatter to g_q/g_k ----------------
// M = B*S = 8192, N = 1152 (=9*128), K = 768. Tile 128x128, 256 threads, 8x8 microtile.
__global__ void __launch_bounds__(256, 2) proj_rope_kernel(
    const float* __restrict__ X, const float* __restrict__ W,
    const float* __restrict__ bias)
{
    __shared__ float As[16][132];   // [k][m], padded
    __shared__ float Bs[16][132];   // [k][n], padded

    const int tid = threadIdx.x;
    const int tx  = tid & 15;
    const int ty  = tid >> 4;
    const int rowBase = blockIdx.y * 128;
    const int e       = blockIdx.x;          // one ent type per block column
    const int colBase = e * 128;

    ull acc[8][4];
#pragma unroll
    for (int j = 0; j < 8; j++)
#pragma unroll
        for (int q = 0; q < 4; q++) acc[j][q] = 0ULL;

    const int lr = tid >> 2;        // 0..63 (row within half-tile)
    const int lc = (tid & 3) * 4;   // 0,4,8,12 (k offset within 16-chunk)
    const float* Ap = X + (size_t)(rowBase + lr) * HID + lc;
    const float* Bp = W + (size_t)(colBase + lr) * HID + lc;

    // register-staged prefetch of k-chunk 0
    float4 pa0 = *(const float4*)(Ap);
    float4 pa1 = *(const float4*)(Ap + (size_t)64 * HID);
    float4 pb0 = *(const float4*)(Bp);
    float4 pb1 = *(const float4*)(Bp + (size_t)64 * HID);

    for (int kb = 0; kb < HID; kb += 16) {
        // commit staged tile to smem (transposed)
        As[lc+0][lr] = pa0.x; As[lc+1][lr] = pa0.y; As[lc+2][lr] = pa0.z; As[lc+3][lr] = pa0.w;
        As[lc+0][lr+64] = pa1.x; As[lc+1][lr+64] = pa1.y; As[lc+2][lr+64] = pa1.z; As[lc+3][lr+64] = pa1.w;
        Bs[lc+0][lr] = pb0.x; Bs[lc+1][lr] = pb0.y; Bs[lc+2][lr] = pb0.z; Bs[lc+3][lr] = pb0.w;
        Bs[lc+0][lr+64] = pb1.x; Bs[lc+1][lr+64] = pb1.y; Bs[lc+2][lr+64] = pb1.z; Bs[lc+3][lr+64] = pb1.w;
        __syncthreads();

        if (kb + 16 < HID) {                 // prefetch next chunk while computing
            pa0 = *(const float4*)(Ap + kb + 16);
            pa1 = *(const float4*)(Ap + (size_t)64 * HID + kb + 16);
            pb0 = *(const float4*)(Bp + kb + 16);
            pb1 = *(const float4*)(Bp + (size_t)64 * HID + kb + 16);
        }

#pragma unroll
        for (int kk = 0; kk < 16; kk++) {
            float a[8];
            *(float4*)(a)     = *(const float4*)(&As[kk][ty * 8]);
            *(float4*)(a + 4) = *(const float4*)(&As[kk][ty * 8 + 4]);
            ull bp[4];
            *(ulonglong2*)(bp)     = *(const ulonglong2*)(&Bs[kk][tx * 8]);
            *(ulonglong2*)(bp + 2) = *(const ulonglong2*)(&Bs[kk][tx * 8 + 4]);
#pragma unroll
            for (int j = 0; j < 8; j++) {
                ull ad = dup2(a[j]);
#pragma unroll
                for (int q = 0; q < 4; q++)
                    acc[j][q] = ffma2(ad, bp[q], acc[j][q]);
            }
        }
        __syncthreads();
    }

    // ---- epilogue: bias + RoPE (partner via shfl.xor 4) + scatter ----
    float bsr[8];
    *(float4*)(bsr)     = *(const float4*)(bias + colBase + tx * 8);
    *(float4*)(bsr + 4) = *(const float4*)(bias + colBase + tx * 8 + 4);

    const bool is_k   = (tx >= 8);
    const int  dbase  = tx * 8 - (is_k ? 64 : 0);   // dim within [0,64)
    const float scale = is_k ? 1.0f : 0.125f;       // fold 1/sqrt(D) into Q
    float* dst = is_k ? g_k : g_q;

#pragma unroll
    for (int j = 0; j < 8; j++) {
        int m  = rowBase + ty * 8 + j;
        int bi = m >> 10;
        int s  = m & (SEQ - 1);

        float v[8];
#pragma unroll
        for (int q = 0; q < 4; q++) unpack2(acc[j][q], v[2 * q], v[2 * q + 1]);
#pragma unroll
        for (int i = 0; i < 8; i++) v[i] += bsr[i];

        const float* cr = g_cos + s * 32 + (dbase >> 1);
        const float* sr = g_sin + s * 32 + (dbase >> 1);
        float outv[8];
#pragma unroll
        for (int i = 0; i < 8; i++) {
            float partner = __shfl_xor_sync(0xffffffffu, v[i], 4);
            int dd = dbase + i;
            float rot = (dd < 32) ? -partner : partner;   // uniform per thread
            outv[i] = (v[i] * cr[i >> 1] + rot * sr[i >> 1]) * scale;
        }
        float* p = dst + (((size_t)(bi * ENT + e) * SEQ + s) * DIM + dbase);
        *(float4*)(p)     = *(float4*)(outv);
        *(float4*)(p + 4) = *(float4*)(outv + 4);
    }
}

// ---------------- Kernel B: per-(b,e) logits = Q @ K^T with masks ----------------
// 72 batches of [1024,64]x[64,1024]; tile 128x128, 256 threads, 8x8 microtile.
__global__ void __launch_bounds__(256, 2) logits_kernel(
    const float* __restrict__ mask, float* __restrict__ out)
{
    __shared__ float Qs[32][132];
    __shared__ float Ks[32][132];

    const int tid = threadIdx.x;
    const int tx  = tid & 15;
    const int ty  = tid >> 4;
    const int z   = blockIdx.z;           // b*ENT + e
    const int bi  = z / ENT;
    const int nBase = blockIdx.x * 128;
    const int mBase = blockIdx.y * 128;
    const float* Q = g_q + (size_t)z * SEQ * DIM;
    const float* K = g_k + (size_t)z * SEQ * DIM;

    ull acc[8][4];
#pragma unroll
    for (int j = 0; j < 8; j++)
#pragma unroll
        for (int q = 0; q < 4; q++) acc[j][q] = 0ULL;

    const int lr = tid >> 3;        // 0..31
    const int lc = (tid & 7) * 4;   // 0..28

#pragma unroll
    for (int kb = 0; kb < DIM; kb += 32) {
#pragma unroll
        for (int l = 0; l < 4; l++) {
            int r = lr + l * 32;
            float4 v = *(const float4*)(Q + (size_t)(mBase + r) * DIM + kb + lc);
            Qs[lc+0][r] = v.x; Qs[lc+1][r] = v.y; Qs[lc+2][r] = v.z; Qs[lc+3][r] = v.w;
            float4 w = *(const float4*)(K + (size_t)(nBase + r) * DIM + kb + lc);
            Ks[lc+0][r] = w.x; Ks[lc+1][r] = w.y; Ks[lc+2][r] = w.z; Ks[lc+3][r] = w.w;
        }
        __syncthreads();
#pragma unroll
        for (int kk = 0; kk < 32; kk++) {
            float a[8];
            *(float4*)(a)     = *(const float4*)(&Qs[kk][ty * 8]);
            *(float4*)(a + 4) = *(const float4*)(&Qs[kk][ty * 8 + 4]);
            ull bp[4];
            *(ulonglong2*)(bp)     = *(const ulonglong2*)(&Ks[kk][tx * 8]);
            *(ulonglong2*)(bp + 2) = *(const ulonglong2*)(&Ks[kk][tx * 8 + 4]);
#pragma unroll
            for (int j = 0; j < 8; j++) {
                ull ad = dup2(a[j]);
#pragma unroll
                for (int q = 0; q < 4; q++)
                    acc[j][q] = ffma2(ad, bp[q], acc[j][q]);
            }
        }
        __syncthreads();
    }

    float pm[8];
    *(float4*)(pm)     = *(const float4*)(mask + (size_t)bi * SEQ + nBase + tx * 8);
    *(float4*)(pm + 4) = *(const float4*)(mask + (size_t)bi * SEQ + nBase + tx * 8 + 4);

#pragma unroll
    for (int j = 0; j < 8; j++) {
        int mg = mBase + ty * 8 + j;
        float res[8];
#pragma unroll
        for (int q = 0; q < 4; q++) unpack2(acc[j][q], res[2 * q], res[2 * q + 1]);
#pragma unroll
        for (int i = 0; i < 8; i++) {
            int ng = nBase + tx * 8 + i;
            float v = res[i];
            v = v * pm[i] - (1.0f - pm[i]) * 10000.0f;   // padding mask (keys)
            if (mg > ng) v -= 10000.0f;                  // causal (below diagonal)
            res[i] = v;
        }
        float* p = out + ((size_t)z * SEQ + mg) * SEQ + nBase + tx * 8;
        *(float4*)(p)     = *(float4*)(res);
        *(float4*)(p + 4) = *(float4*)(res + 4);
    }
}

// ---------------- launch ----------------
extern "C" void kernel_launch(void* const* d_in, const int* in_sizes, int n_in,
                              void* d_out, int out_size) {
    (void)in_sizes; (void)n_in; (void)out_size;
    const float* X    = (const float*)d_in[0];   // [8,1024,768]
    const float* mask = (const float*)d_in[1];   // [8,1024]
    const float* W    = (const float*)d_in[2];   // [1152,768]
    const float* bias = (const float*)d_in[3];   // [1152]
    float* out = (float*)d_out;                  // [8,9,1024,1024]

    rope_table_kernel<<<(SEQ * 32) / 256, 256>>>();

    dim3 gA(ENT, (BATCH * SEQ) / 128);           // 9 x 64
    proj_rope_kernel<<<gA, 256>>>(X, W, bias);

    dim3 gB(SEQ / 128, SEQ / 128, BATCH * ENT);  // 8 x 8 x 72
    logits_kernel<<<gB, 256>>>(mask, out);
}